// round 2
// baseline (speedup 1.0000x reference)
#include <cuda_runtime.h>
#include <math.h>

#define IMG   512
#define NVIEW 180
#define NPIX  (IMG * IMG)

typedef unsigned long long ull;

// Interleaved copy of both batch images: g_xi[y*512+x] = (batch0, batch1).
__device__ float2 g_xi[NPIX];
// Per-view (cos, sin) fp32, matching np.cos(np.linspace(0,pi,180,endpoint=False)).astype(f32)
__device__ float2 g_trig[NVIEW];

struct ViewList { unsigned short v[NVIEW]; };

// ---- packed f32x2 helpers (sm_100+) ----
__device__ __forceinline__ ull pk(float lo, float hi) {
    ull r; asm("mov.b64 %0,{%1,%2};" : "=l"(r) : "f"(lo), "f"(hi)); return r;
}
__device__ __forceinline__ void upk(ull p, float& lo, float& hi) {
    asm("mov.b64 {%0,%1},%2;" : "=f"(lo), "=f"(hi) : "l"(p));
}
__device__ __forceinline__ ull mul2(ull a, ull b) {
    ull r; asm("mul.rn.f32x2 %0,%1,%2;" : "=l"(r) : "l"(a), "l"(b)); return r;
}
__device__ __forceinline__ ull add2(ull a, ull b) {
    ull r; asm("add.rn.f32x2 %0,%1,%2;" : "=l"(r) : "l"(a), "l"(b)); return r;
}
__device__ __forceinline__ ull fma2(ull a, ull b, ull c) {
    ull r; asm("fma.rn.f32x2 %0,%1,%2,%3;" : "=l"(r) : "l"(a), "l"(b), "l"(c)); return r;
}

__global__ void prep_kernel(const float* __restrict__ x) {
    int i = blockIdx.x * blockDim.x + threadIdx.x;
    if (i < NPIX) {
        g_xi[i] = make_float2(x[i], x[i + NPIX]);
    }
    if (i < NVIEW) {
        double th = (double)i * (M_PI / 180.0);
        g_trig[i] = make_float2((float)cos(th), (float)sin(th));
    }
}

// Warp tile: W lanes along w, H = 32/W lanes along h. Each warp produces 16
// outputs (NC = 16/W chunks of W). Every thread does 256 samples; 16
// independent gathers in flight per outer iteration for all shapes.
template<int LOGW>
__global__ __launch_bounds__(128) void radon_kernel(float* __restrict__ out, ViewList vl) {
    constexpr int W  = 1 << LOGW;
    constexpr int H  = 32 >> LOGW;
    constexpr int NC = 16 / W;       // w-chunks per warp
    constexpr int TSTEP = W;         // h-steps per outer iter (TSTEP*NC == 16)

    const int v    = vl.v[blockIdx.y];
    const int lane = threadIdx.x & 31;
    const int warp = threadIdx.x >> 5;
    const int wi   = lane & (W - 1);
    const int hi   = lane >> LOGW;
    const int wbase = (blockIdx.x << 6) + (warp << 4);

    const float2 cs = g_trig[v];
    const float c = cs.x, s = cs.y;
    const ull csP  = pk(s, c);          // (s, c)
    const ull sgnP = pk(-1.0f, 1.0f);   // gx = P - s*gy0 ; gy = S + c*gy0

    ull PS[NC], acc[NC];
    #pragma unroll
    for (int j = 0; j < NC; j++) {
        int w = wbase + j * W + wi;
        // gx0 = (2w+1)/512 - 1, exact FMA
        float gx0 = __fmaf_rn((float)w, 1.0f / 256.0f, -511.0f / 512.0f);
        PS[j] = pk(__fmul_rn(c, gx0), __fmul_rn(s, gx0));   // (P, S)
        acc[j] = 0ull;
    }

    // gy0 walks h = hi, hi+H, hi+2H, ... ; all values & increments exact in fp32
    float gy0 = __fmaf_rn((float)hi, 1.0f / 256.0f, -511.0f / 512.0f);
    ull gy0p = pk(gy0, gy0);
    const ull stepP = pk((float)H / 256.0f, (float)H / 256.0f);

    const float MAGIC = 12582912.0f;      // 1.5*2^23: magic round-half-even
    const float BOUND = 12583424.0f;      // MAGIC + 512

    for (int to = 0; to < 16; to++) {
        #pragma unroll
        for (int tt = 0; tt < TSTEP; tt++) {
            ull qp = mul2(gy0p, csP);         // (s*gy0, c*gy0), each rounded once
            gy0p = add2(gy0p, stepP);         // exact
            #pragma unroll
            for (int j = 0; j < NC; j++) {
                ull gp = fma2(qp, sgnP, PS[j]);   // (fl(P - s*gy0), fl(S + c*gy0))
                float gx, gy; upk(gp, gx, gy);
                gx = fmaxf(gx, -1.0f);            // lower clamp semantically required
                gy = fmaxf(gy, -1.0f);            // (upper clamp provably redundant)
                // ((g+1)*512-1)*0.5 == fma(g+1,256,-0.5) exactly; +MAGIC = rint (ties-even)
                float rx = __fadd_rn(__fmaf_rn(__fadd_rn(gx, 1.0f), 256.0f, -0.5f), MAGIC);
                float ry = __fadd_rn(__fmaf_rn(__fadd_rn(gy, 1.0f), 256.0f, -0.5f), MAGIC);
                // ix,iy >= 0 guaranteed; valid iff both < 512
                bool ok = fmaxf(rx, ry) < BOUND;
                // iy*512 + ix directly from magic bit patterns (mod 2^32)
                unsigned idx = (unsigned)__float_as_int(ry) * 512u
                             + (unsigned)__float_as_int(rx)
                             - 0x4B400000u * 513u;
                ull val = 0ull;
                if (ok) val = __ldg((const ull*)((const char*)g_xi + (size_t)idx * 8u));
                acc[j] = add2(acc[j], val);
            }
        }
    }

    // reduce over the H h-lanes of each chunk, then write
    #pragma unroll
    for (int j = 0; j < NC; j++) {
        float a0, a1; upk(acc[j], a0, a1);
        #pragma unroll
        for (int off = W; off < 32; off <<= 1) {
            a0 += __shfl_xor_sync(0xffffffffu, a0, off);
            a1 += __shfl_xor_sync(0xffffffffu, a1, off);
        }
        if (hi == 0) {
            int w = wbase + j * W + wi;
            out[v * IMG + w]               = a0 * (1.0f / 512.0f);
            out[NVIEW * IMG + v * IMG + w] = a1 * (1.0f / 512.0f);
        }
    }
}

extern "C" void kernel_launch(void* const* d_in, const int* in_sizes, int n_in,
                              void* d_out, int out_size) {
    const float* x = (const float*)d_in[0];
    float* out = (float*)d_out;

    prep_kernel<<<(NPIX + 255) / 256, 256>>>(x);

    // Host-side per-view tile-shape selection (perf-only; any shape is correct).
    ViewList lists[5];
    int cnt[5] = {0, 0, 0, 0, 0};
    for (int v = 0; v < NVIEW; v++) {
        double th = (double)v * (M_PI / 180.0);
        double ac = fabs(cos(th)), as = fabs(sin(th));
        int best = 0; double bestcost = 1e30;
        for (int lw = 0; lw <= 4; lw++) {
            double W = (double)(1 << lw), H = 32.0 / W;
            double rows = W * as + H * ac + 1.0;
            double segB = (W * ac + H * as) * 8.0 + 8.0;
            double cost = rows * (1.0 + segB / 128.0);
            if (cost < bestcost) { bestcost = cost; best = lw; }
        }
        lists[best].v[cnt[best]++] = (unsigned short)v;
    }

    for (int lw = 0; lw <= 4; lw++) {
        if (cnt[lw] == 0) continue;
        dim3 grid(IMG / 64, cnt[lw]);
        switch (lw) {
            case 0: radon_kernel<0><<<grid, 128>>>(out, lists[0]); break;
            case 1: radon_kernel<1><<<grid, 128>>>(out, lists[1]); break;
            case 2: radon_kernel<2><<<grid, 128>>>(out, lists[2]); break;
            case 3: radon_kernel<3><<<grid, 128>>>(out, lists[3]); break;
            case 4: radon_kernel<4><<<grid, 128>>>(out, lists[4]); break;
        }
    }
}

// round 3
// speedup vs baseline: 2.5770x; 2.5770x over previous
#include <cuda_runtime.h>
#include <math.h>

#define IMG   512
#define NVIEW 180
#define NPIX  (IMG * IMG)

typedef unsigned long long ull;

// Interleaved copy of both batch images: g_xi[y*512+x] = (batch0, batch1).
__device__ float2 g_xi[NPIX];
// Per-view (cos, sin) fp32, matching np.cos(np.linspace(0,pi,180,endpoint=False)).astype(f32)
__device__ float2 g_trig[NVIEW];

struct ViewShapes { unsigned char lw[NVIEW]; };

// ---- packed f32x2 helpers (sm_100+) ----
__device__ __forceinline__ ull pk(float lo, float hi) {
    ull r; asm("mov.b64 %0,{%1,%2};" : "=l"(r) : "f"(lo), "f"(hi)); return r;
}
__device__ __forceinline__ void upk(ull p, float& lo, float& hi) {
    asm("mov.b64 {%0,%1},%2;" : "=f"(lo), "=f"(hi) : "l"(p));
}
__device__ __forceinline__ ull mul2(ull a, ull b) {
    ull r; asm("mul.rn.f32x2 %0,%1,%2;" : "=l"(r) : "l"(a), "l"(b)); return r;
}
__device__ __forceinline__ ull add2(ull a, ull b) {
    ull r; asm("add.rn.f32x2 %0,%1,%2;" : "=l"(r) : "l"(a), "l"(b)); return r;
}
__device__ __forceinline__ ull fma2(ull a, ull b, ull c) {
    ull r; asm("fma.rn.f32x2 %0,%1,%2,%3;" : "=l"(r) : "l"(a), "l"(b), "l"(c)); return r;
}

__global__ void prep_kernel(const float* __restrict__ x) {
    int i = blockIdx.x * blockDim.x + threadIdx.x;
    if (i < NPIX) {
        g_xi[i] = make_float2(x[i], x[i + NPIX]);
    }
    if (i < NVIEW) {
        double th = (double)i * (M_PI / 180.0);
        g_trig[i] = make_float2((float)cos(th), (float)sin(th));
    }
}

// Warp tile: W lanes along w, H = 32/W lanes along h. Each warp produces 16
// outputs (NC = 16/W chunks of W). Every thread does 256 samples; 16
// independent gathers in flight per outer iteration for all shapes.
template<int LOGW>
__device__ __forceinline__ void radon_body(float* __restrict__ out, int v) {
    constexpr int W  = 1 << LOGW;
    constexpr int NC = 16 / W;       // w-chunks per warp
    constexpr int TSTEP = W;         // h-steps per outer iter (TSTEP*NC == 16)
    constexpr int H  = 32 >> LOGW;

    const int lane = threadIdx.x & 31;
    const int warp = threadIdx.x >> 5;
    const int wi   = lane & (W - 1);
    const int hi   = lane >> LOGW;
    const int wbase = (blockIdx.x << 6) + (warp << 4);

    const float2 cs = g_trig[v];
    const float c = cs.x, s = cs.y;
    const ull csP  = pk(s, c);          // (s, c)
    const ull sgnP = pk(-1.0f, 1.0f);   // gx = P - s*gy0 ; gy = S + c*gy0

    ull PS[NC], acc[NC];
    #pragma unroll
    for (int j = 0; j < NC; j++) {
        int w = wbase + j * W + wi;
        // gx0 = (2w+1)/512 - 1, exact FMA
        float gx0 = __fmaf_rn((float)w, 1.0f / 256.0f, -511.0f / 512.0f);
        PS[j] = pk(__fmul_rn(c, gx0), __fmul_rn(s, gx0));   // (P, S)
        acc[j] = 0ull;
    }

    // gy0 walks h = hi, hi+H, hi+2H, ... ; all values & increments exact in fp32
    float gy0 = __fmaf_rn((float)hi, 1.0f / 256.0f, -511.0f / 512.0f);
    ull gy0p = pk(gy0, gy0);
    const ull stepP = pk((float)H / 256.0f, (float)H / 256.0f);

    const float MAGIC = 12582912.0f;      // 1.5*2^23: magic round-half-even
    const float BOUND = 12583424.0f;      // MAGIC + 512

    for (int to = 0; to < 16; to++) {
        #pragma unroll
        for (int tt = 0; tt < TSTEP; tt++) {
            ull qp = mul2(gy0p, csP);         // (s*gy0, c*gy0), each rounded once
            gy0p = add2(gy0p, stepP);         // exact
            #pragma unroll
            for (int j = 0; j < NC; j++) {
                ull gp = fma2(qp, sgnP, PS[j]);   // (fl(P - s*gy0), fl(S + c*gy0))
                float gx, gy; upk(gp, gx, gy);
                gx = fmaxf(gx, -1.0f);            // lower clamp semantically required
                gy = fmaxf(gy, -1.0f);            // (upper clamp provably redundant)
                // ((g+1)*512-1)*0.5 == fma(g+1,256,-0.5) exactly; +MAGIC = rint (ties-even)
                float rx = __fadd_rn(__fmaf_rn(__fadd_rn(gx, 1.0f), 256.0f, -0.5f), MAGIC);
                float ry = __fadd_rn(__fmaf_rn(__fadd_rn(gy, 1.0f), 256.0f, -0.5f), MAGIC);
                // ix,iy >= 0 guaranteed; valid iff both < 512
                bool ok = fmaxf(rx, ry) < BOUND;
                // iy*512 + ix directly from magic bit patterns (mod 2^32)
                unsigned idx = (unsigned)__float_as_int(ry) * 512u
                             + (unsigned)__float_as_int(rx)
                             - 0x4B400000u * 513u;
                ull val = 0ull;
                if (ok) val = __ldg((const ull*)((const char*)g_xi + (size_t)idx * 8u));
                acc[j] = add2(acc[j], val);
            }
        }
    }

    // reduce over the H h-lanes of each chunk, then write
    #pragma unroll
    for (int j = 0; j < NC; j++) {
        float a0, a1; upk(acc[j], a0, a1);
        #pragma unroll
        for (int off = W; off < 32; off <<= 1) {
            a0 += __shfl_xor_sync(0xffffffffu, a0, off);
            a1 += __shfl_xor_sync(0xffffffffu, a1, off);
        }
        if (hi == 0) {
            int w = wbase + j * W + wi;
            out[v * IMG + w]               = a0 * (1.0f / 512.0f);
            out[NVIEW * IMG + v * IMG + w] = a1 * (1.0f / 512.0f);
        }
    }
}

// Single fat launch: all 180 views; per-block uniform dispatch on tile shape.
__global__ __launch_bounds__(128) void radon_kernel(float* __restrict__ out, ViewShapes sh) {
    const int v = blockIdx.y;
    switch (sh.lw[v]) {
        case 0: radon_body<0>(out, v); break;
        case 1: radon_body<1>(out, v); break;
        case 2: radon_body<2>(out, v); break;
        case 3: radon_body<3>(out, v); break;
        default: radon_body<4>(out, v); break;
    }
}

extern "C" void kernel_launch(void* const* d_in, const int* in_sizes, int n_in,
                              void* d_out, int out_size) {
    const float* x = (const float*)d_in[0];
    float* out = (float*)d_out;

    prep_kernel<<<(NPIX + 255) / 256, 256>>>(x);

    // Host-side per-view tile-shape selection (perf-only; any shape is correct).
    ViewShapes sh;
    for (int v = 0; v < NVIEW; v++) {
        double th = (double)v * (M_PI / 180.0);
        double ac = fabs(cos(th)), as = fabs(sin(th));
        int best = 0; double bestcost = 1e30;
        for (int lw = 0; lw <= 4; lw++) {
            double W = (double)(1 << lw), H = 32.0 / W;
            double rows = W * as + H * ac + 1.0;
            double segB = (W * ac + H * as) * 8.0 + 8.0;
            double cost = rows * (1.0 + segB / 128.0);
            if (cost < bestcost) { bestcost = cost; best = lw; }
        }
        sh.lw[v] = (unsigned char)best;
    }

    dim3 grid(IMG / 64, NVIEW);
    radon_kernel<<<grid, 128>>>(out, sh);
}

// round 4
// speedup vs baseline: 3.4726x; 1.3475x over previous
#include <cuda_runtime.h>
#include <math.h>

#define IMG   512
#define NVIEW 180
#define NPIX  (IMG * IMG)

typedef unsigned long long ull;

// Interleaved copy of both batch images: g_xi[y*512+x] = (batch0, batch1).
__device__ float2 g_xi[NPIX];
// Per-view (cos, sin) fp32, matching np.cos(np.linspace(0,pi,180,endpoint=False)).astype(f32)
__device__ float2 g_trig[NVIEW];

struct ViewShapes { unsigned char lw[NVIEW]; };

// ---- packed f32x2 helpers (sm_100+) ----
__device__ __forceinline__ ull pk(float lo, float hi) {
    ull r; asm("mov.b64 %0,{%1,%2};" : "=l"(r) : "f"(lo), "f"(hi)); return r;
}
__device__ __forceinline__ void upk(ull p, float& lo, float& hi) {
    asm("mov.b64 {%0,%1},%2;" : "=f"(lo), "=f"(hi) : "l"(p));
}
__device__ __forceinline__ ull mul2(ull a, ull b) {
    ull r; asm("mul.rn.f32x2 %0,%1,%2;" : "=l"(r) : "l"(a), "l"(b)); return r;
}
__device__ __forceinline__ ull add2(ull a, ull b) {
    ull r; asm("add.rn.f32x2 %0,%1,%2;" : "=l"(r) : "l"(a), "l"(b)); return r;
}
__device__ __forceinline__ ull fma2(ull a, ull b, ull c) {
    ull r; asm("fma.rn.f32x2 %0,%1,%2,%3;" : "=l"(r) : "l"(a), "l"(b), "l"(c)); return r;
}

__global__ void prep_kernel(const float* __restrict__ x) {
    int i = blockIdx.x * blockDim.x + threadIdx.x;
    if (i < NPIX) {
        g_xi[i] = make_float2(x[i], x[i + NPIX]);
    }
    if (i < NVIEW) {
        double th = (double)i * (M_PI / 180.0);
        g_trig[i] = make_float2((float)cos(th), (float)sin(th));
    }
}

// Warp tile: W lanes along w, H = 32/W lanes along h; each warp makes 16
// outputs (NC = 16/W chunks). Uniform loop structure: 32 outer iterations,
// G = W/2 h-steps per iteration -> G*NC = 8 gathers in flight per thread.
template<int LOGW>
__device__ __forceinline__ void radon_body(float* __restrict__ out, int v) {
    constexpr int W  = 1 << LOGW;
    constexpr int H  = 32 >> LOGW;
    constexpr int NC = 16 / W;     // w-chunks per warp
    constexpr int G  = W / 2;      // h-steps per outer iter (G*NC == 8)

    const int lane = threadIdx.x & 31;
    const int warp = threadIdx.x >> 5;
    const int wi   = lane & (W - 1);
    const int hi   = lane >> LOGW;
    const int wbase = (blockIdx.x << 6) + (warp << 4);

    const float2 cs = g_trig[v];
    const float c = cs.x, s = cs.y;
    const ull csP  = pk(s, c);          // (s, c)
    const ull sgnP = pk(-1.0f, 1.0f);   // gx = P - s*gy0 ; gy = S + c*gy0

    ull PS[NC], acc[NC];
    #pragma unroll
    for (int j = 0; j < NC; j++) {
        int w = wbase + j * W + wi;
        float gx0 = __fmaf_rn((float)w, 1.0f / 256.0f, -511.0f / 512.0f);  // exact
        PS[j] = pk(__fmul_rn(c, gx0), __fmul_rn(s, gx0));   // (P, S)
        acc[j] = 0ull;
    }

    // gy0 walks h = hi, hi+H, ... ; all values and increments exact in fp32
    float gy0 = __fmaf_rn((float)hi, 1.0f / 256.0f, -511.0f / 512.0f);
    ull gy0p = pk(gy0, gy0);
    const ull stepP = pk((float)H / 256.0f, (float)H / 256.0f);

    const float MAGIC = 12582912.0f;      // 1.5*2^23: magic round-half-even
    const float BOUND = 12583424.0f;      // MAGIC + 512

    #pragma unroll 1
    for (int to = 0; to < 32; to++) {
        #pragma unroll
        for (int g = 0; g < G; g++) {
            ull qp = mul2(gy0p, csP);         // (s*gy0, c*gy0), each rounded once
            gy0p = add2(gy0p, stepP);         // exact
            #pragma unroll
            for (int j = 0; j < NC; j++) {
                ull gp = fma2(qp, sgnP, PS[j]);   // (fl(P - s*gy0), fl(S + c*gy0))
                float gx, gy; upk(gp, gx, gy);
                gx = fmaxf(gx, -1.0f);            // lower clamp semantically required
                gy = fmaxf(gy, -1.0f);            // (upper clamp provably redundant)
                // ((g+1)*512-1)*0.5 == fma(g+1,256,-0.5) exactly; +MAGIC = rint(ties-even)
                float rx = __fadd_rn(__fmaf_rn(__fadd_rn(gx, 1.0f), 256.0f, -0.5f), MAGIC);
                float ry = __fadd_rn(__fmaf_rn(__fadd_rn(gy, 1.0f), 256.0f, -0.5f), MAGIC);
                bool ok = fmaxf(rx, ry) < BOUND;  // ix,iy >= 0 guaranteed by clamp
                // iy*512 + ix directly from magic bit patterns (mod 2^32)
                unsigned idx = (unsigned)__float_as_int(ry) * 512u
                             + (unsigned)__float_as_int(rx)
                             - 0x4B400000u * 513u;
                ull val = 0ull;
                if (ok) val = __ldg((const ull*)((const char*)g_xi + (size_t)idx * 8u));
                acc[j] = add2(acc[j], val);
            }
        }
    }

    // reduce over the H h-lanes of each chunk, then write
    #pragma unroll
    for (int j = 0; j < NC; j++) {
        float a0, a1; upk(acc[j], a0, a1);
        #pragma unroll
        for (int off = W; off < 32; off <<= 1) {
            a0 += __shfl_xor_sync(0xffffffffu, a0, off);
            a1 += __shfl_xor_sync(0xffffffffu, a1, off);
        }
        if (hi == 0) {
            int w = wbase + j * W + wi;
            out[v * IMG + w]               = a0 * (1.0f / 512.0f);
            out[NVIEW * IMG + v * IMG + w] = a1 * (1.0f / 512.0f);
        }
    }
}

// Single fat launch: all 180 views; per-block uniform dispatch on tile shape.
__global__ __launch_bounds__(128, 8) void radon_kernel(float* __restrict__ out, ViewShapes sh) {
    const int v = blockIdx.y;
    switch (sh.lw[v]) {
        case 2: radon_body<2>(out, v); break;
        case 3: radon_body<3>(out, v); break;
        default: radon_body<4>(out, v); break;
    }
}

extern "C" void kernel_launch(void* const* d_in, const int* in_sizes, int n_in,
                              void* d_out, int out_size) {
    const float* x = (const float*)d_in[0];
    float* out = (float*)d_out;

    prep_kernel<<<(NPIX + 255) / 256, 256>>>(x);

    // Host-side per-view tile-shape selection (perf-only; any shape is correct).
    ViewShapes sh;
    for (int v = 0; v < NVIEW; v++) {
        double th = (double)v * (M_PI / 180.0);
        double ac = fabs(cos(th)), as = fabs(sin(th));
        int best = 2; double bestcost = 1e30;
        for (int lw = 2; lw <= 4; lw++) {
            double W = (double)(1 << lw), H = 32.0 / W;
            double rows = W * as + H * ac + 1.0;
            double segB = (W * ac + H * as) * 8.0 + 8.0;
            double cost = rows * (1.0 + segB / 128.0);
            if (cost < bestcost) { bestcost = cost; best = lw; }
        }
        sh.lw[v] = (unsigned char)best;
    }

    dim3 grid(IMG / 64, NVIEW);
    radon_kernel<<<grid, 128>>>(out, sh);
}

// round 5
// speedup vs baseline: 3.8830x; 1.1182x over previous
#include <cuda_runtime.h>
#include <math.h>

#define IMG   512
#define NVIEW 180
#define NPIX  (IMG * IMG)

typedef unsigned long long ull;

// Interleaved copy of both batch images: g_xi[y*512+x] = (batch0, batch1).
__device__ float2 g_xi[NPIX];
// Per-view (cos, sin) fp32, matching np.cos(np.linspace(0,pi,180,endpoint=False)).astype(f32)
__device__ float2 g_trig[NVIEW];

struct ViewShapes { unsigned char lw[NVIEW]; };

// ---- packed f32x2 helpers (sm_100+) ----
__device__ __forceinline__ ull pk(float lo, float hi) {
    ull r; asm("mov.b64 %0,{%1,%2};" : "=l"(r) : "f"(lo), "f"(hi)); return r;
}
__device__ __forceinline__ void upk(ull p, float& lo, float& hi) {
    asm("mov.b64 {%0,%1},%2;" : "=f"(lo), "=f"(hi) : "l"(p));
}
__device__ __forceinline__ ull mul2(ull a, ull b) {
    ull r; asm("mul.rn.f32x2 %0,%1,%2;" : "=l"(r) : "l"(a), "l"(b)); return r;
}
__device__ __forceinline__ ull add2(ull a, ull b) {
    ull r; asm("add.rn.f32x2 %0,%1,%2;" : "=l"(r) : "l"(a), "l"(b)); return r;
}

__global__ void prep_kernel(const float* __restrict__ x) {
    int i = blockIdx.x * blockDim.x + threadIdx.x;
    if (i < NPIX) {
        g_xi[i] = make_float2(x[i], x[i + NPIX]);
    }
    if (i < NVIEW) {
        double th = (double)i * (M_PI / 180.0);
        g_trig[i] = make_float2((float)cos(th), (float)sin(th));
    }
}

// Warp tile: W lanes along w, H = 32/W lanes along h; each warp makes 16
// outputs (NC = 16/W chunks). Uniform loop: 64 outer iterations, G = W/4
// h-steps each -> G*NC = 4 gathers in flight per thread (low reg pressure).
template<int LOGW>
__device__ __forceinline__ void radon_body(float* __restrict__ out, int v) {
    constexpr int W  = 1 << LOGW;
    constexpr int H  = 32 >> LOGW;
    constexpr int NC = 16 / W;     // w-chunks per warp
    constexpr int G  = W / 4;      // h-steps per outer iter (G*NC == 4)

    const int lane = threadIdx.x & 31;
    const int warp = threadIdx.x >> 5;
    const int wi   = lane & (W - 1);
    const int hi   = lane >> LOGW;
    const int wbase = (blockIdx.x << 6) + (warp << 4);

    const float2 cs = g_trig[v];
    const float c = cs.x, s = cs.y;
    const ull csP  = pk(-s, c);         // qp = (-s*gy0, c*gy0); fl(-s*gy0) == -fl(s*gy0)

    ull PS[NC], acc[NC];
    #pragma unroll
    for (int j = 0; j < NC; j++) {
        int w = wbase + j * W + wi;
        float gx0 = __fmaf_rn((float)w, 1.0f / 256.0f, -511.0f / 512.0f);  // exact
        PS[j] = pk(__fmul_rn(c, gx0), __fmul_rn(s, gx0));   // (P, S)
        acc[j] = 0ull;
    }

    // gy0 walks h = hi, hi+H, ... ; all values and increments exact in fp32
    float gy0 = __fmaf_rn((float)hi, 1.0f / 256.0f, -511.0f / 512.0f);
    ull gy0p = pk(gy0, gy0);
    const ull stepP = pk((float)H / 256.0f, (float)H / 256.0f);

    const float MAGIC = 12582912.0f;      // 1.5*2^23: magic round-half-even
    const float BOUND = 12583424.0f;      // MAGIC + 512

    #pragma unroll 1
    for (int to = 0; to < 64; to++) {
        #pragma unroll
        for (int g = 0; g < G; g++) {
            ull qp = mul2(gy0p, csP);         // (-s*gy0, c*gy0), each rounded once
            gy0p = add2(gy0p, stepP);         // exact
            #pragma unroll
            for (int j = 0; j < NC; j++) {
                ull gp = add2(PS[j], qp);     // (fl(P - fl(s*gy0)), fl(S + fl(c*gy0)))
                float gx, gy; upk(gp, gx, gy);
                gx = fmaxf(gx, -1.0f);            // lower clamp semantically required
                gy = fmaxf(gy, -1.0f);            // (upper clamp provably redundant)
                // ((g+1)*512-1)*0.5 == fma(g+1,256,-0.5) exactly; +MAGIC = rint(ties-even)
                float rx = __fadd_rn(__fmaf_rn(__fadd_rn(gx, 1.0f), 256.0f, -0.5f), MAGIC);
                float ry = __fadd_rn(__fmaf_rn(__fadd_rn(gy, 1.0f), 256.0f, -0.5f), MAGIC);
                bool ok = fmaxf(rx, ry) < BOUND;  // ix,iy >= 0 guaranteed by clamp
                // iy*512 + ix directly from magic bit patterns (mod 2^32)
                unsigned idx = (unsigned)__float_as_int(ry) * 512u
                             + (unsigned)__float_as_int(rx)
                             - 0x4B400000u * 513u;
                ull val = 0ull;
                if (ok) val = __ldg((const ull*)((const char*)g_xi + (size_t)idx * 8u));
                acc[j] = add2(acc[j], val);
            }
        }
    }

    // reduce over the H h-lanes of each chunk, then write
    #pragma unroll
    for (int j = 0; j < NC; j++) {
        float a0, a1; upk(acc[j], a0, a1);
        #pragma unroll
        for (int off = W; off < 32; off <<= 1) {
            a0 += __shfl_xor_sync(0xffffffffu, a0, off);
            a1 += __shfl_xor_sync(0xffffffffu, a1, off);
        }
        if (hi == 0) {
            int w = wbase + j * W + wi;
            out[v * IMG + w]               = a0 * (1.0f / 512.0f);
            out[NVIEW * IMG + v * IMG + w] = a1 * (1.0f / 512.0f);
        }
    }
}

// Single fat launch: all 180 views; per-block uniform dispatch on tile shape.
// 1440 blocks <= 10 blocks/SM * 148 SMs = 1480 slots -> single wave.
__global__ __launch_bounds__(128, 10) void radon_kernel(float* __restrict__ out, ViewShapes sh) {
    const int v = blockIdx.y;
    switch (sh.lw[v]) {
        case 2: radon_body<2>(out, v); break;
        case 3: radon_body<3>(out, v); break;
        default: radon_body<4>(out, v); break;
    }
}

extern "C" void kernel_launch(void* const* d_in, const int* in_sizes, int n_in,
                              void* d_out, int out_size) {
    const float* x = (const float*)d_in[0];
    float* out = (float*)d_out;

    prep_kernel<<<(NPIX + 255) / 256, 256>>>(x);

    // Host-side per-view tile-shape selection (perf-only; any shape is correct).
    ViewShapes sh;
    for (int v = 0; v < NVIEW; v++) {
        double th = (double)v * (M_PI / 180.0);
        double ac = fabs(cos(th)), as = fabs(sin(th));
        int best = 2; double bestcost = 1e30;
        for (int lw = 2; lw <= 4; lw++) {
            double W = (double)(1 << lw), H = 32.0 / W;
            double rows = W * as + H * ac + 1.0;
            double segB = (W * ac + H * as) * 8.0 + 8.0;
            double cost = rows * (1.0 + segB / 128.0);
            if (cost < bestcost) { bestcost = cost; best = lw; }
        }
        sh.lw[v] = (unsigned char)best;
    }

    dim3 grid(IMG / 64, NVIEW);
    radon_kernel<<<grid, 128>>>(out, sh);
}